// round 6
// baseline (speedup 1.0000x reference)
#include <cuda_runtime.h>
#include <cstdint>

#define NB 2
#define NH 16
#define NS 2048
#define ND 64

// Scratch (allocation-free rule: __device__ globals)
__device__ float g_Q[NB*NH*NS*ND];
__device__ float g_K[NB*NH*NS*ND];
__device__ float g_V[NB*NH*NS*ND];

// ---------------------------------------------------------------------------
// helpers
// ---------------------------------------------------------------------------
__device__ __forceinline__ uint32_t f2tf32(float x) {
    uint32_t r;
    asm("cvt.rna.tf32.f32 %0, %1;" : "=r"(r) : "f"(x));
    return r;
}
// m16n8k8 tf32 warp MMA, fp32 accumulate (base ISA, works on sm_103 target)
__device__ __forceinline__ void mma8(float* c, const uint32_t* a,
                                     uint32_t b0, uint32_t b1) {
    asm volatile(
        "mma.sync.aligned.m16n8k8.row.col.f32.tf32.tf32.f32 "
        "{%0,%1,%2,%3}, {%4,%5,%6,%7}, {%8,%9}, {%0,%1,%2,%3};"
        : "+f"(c[0]), "+f"(c[1]), "+f"(c[2]), "+f"(c[3])
        : "r"(a[0]), "r"(a[1]), "r"(a[2]), "r"(a[3]), "r"(b0), "r"(b1));
}

// ---------------------------------------------------------------------------
// JAX partitionable threefry2x32, key=(0,42): bits[i] = o0^o1, counter (0,i)
// Dual-cipher version: elements e and e+1 interleaved (ILP) with round adds
// routed via mad.lo.u32 (fma pipe) to offload the saturated alu pipe.
// ---------------------------------------------------------------------------
__device__ __forceinline__ uint32_t rotl32(uint32_t x, int r) {
    return __funnelshift_l(x, x, r);
}
#define ADDF(a, b) asm("mad.lo.u32 %0, %1, 1, %0;" : "+r"(a) : "r"(b))

#define KEEP_THRESH 0xE6666600u   // uniform < 0.9f, exact integer reduction

// returns bit0 = keep(e), bit1 = keep(e+1)
__device__ __forceinline__ uint32_t keep2(uint32_t e) {
    const uint32_t k0 = 0u, k1 = 42u, k2 = 0u ^ 42u ^ 0x1BD11BDAu;
    uint32_t a0 = k0,      b0 = e + k1;
    uint32_t a1 = k0,      b1 = e + 1u + k1;
#define TF_R2(r) { ADDF(a0, b0); ADDF(a1, b1);                                 \
                   b0 = rotl32(b0, (r)); b1 = rotl32(b1, (r));                 \
                   b0 ^= a0; b1 ^= a1; }
    TF_R2(13) TF_R2(15) TF_R2(26) TF_R2(6)
    a0 += k1; a1 += k1; b0 += k2 + 1u; b1 += k2 + 1u;
    TF_R2(17) TF_R2(29) TF_R2(16) TF_R2(24)
    a0 += k2; a1 += k2; b0 += k0 + 2u; b1 += k0 + 2u;
    TF_R2(13) TF_R2(15) TF_R2(26) TF_R2(6)
    a0 += k0; a1 += k0; b0 += k1 + 3u; b1 += k1 + 3u;
    TF_R2(17) TF_R2(29) TF_R2(16) TF_R2(24)
    a0 += k1; a1 += k1; b0 += k2 + 4u; b1 += k2 + 4u;
    TF_R2(13) TF_R2(15) TF_R2(26) TF_R2(6)
    a0 += k2; a1 += k2; b0 += k0 + 5u; b1 += k0 + 5u;
#undef TF_R2
    uint32_t r = ((a0 ^ b0) < KEEP_THRESH) ? 1u : 0u;
    r |= ((a1 ^ b1) < KEEP_THRESH) ? 2u : 0u;
    return r;
}

// ---------------------------------------------------------------------------
// QKV projection (validated in R2): Y = X @ W^T + b, output [B,H,S,D]
// ---------------------------------------------------------------------------
__global__ void proj_kernel(const float* __restrict__ X,
                            const float* __restrict__ W,
                            const float* __restrict__ bias, int which) {
    __shared__ __align__(16) float Xt[64][68];
    __shared__ __align__(16) float Wt[64][68];
    __shared__ float bs[64];
    float* Y = (which == 0) ? g_Q : (which == 1) ? g_K : g_V;

    int tid = threadIdx.x;
    if (tid < 64) bs[tid] = bias[tid];
    int r0 = blockIdx.x * 64;

#pragma unroll
    for (int r = 0; r < 4; r++) {
        int fidx = tid + r * 256;
        int row = fidx >> 4, dg = fidx & 15;
        int pg = (((row >> 2) ^ dg) << 2) + (row & 3);
        float4 w4 = reinterpret_cast<const float4*>(W)[fidx];
        Wt[4*dg+0][pg] = w4.x; Wt[4*dg+1][pg] = w4.y;
        Wt[4*dg+2][pg] = w4.z; Wt[4*dg+3][pg] = w4.w;
        float4 x4 = reinterpret_cast<const float4*>(X + (size_t)(r0 + row) * 64)[dg];
        Xt[4*dg+0][pg] = x4.x; Xt[4*dg+1][pg] = x4.y;
        Xt[4*dg+2][pg] = x4.z; Xt[4*dg+3][pg] = x4.w;
    }
    __syncthreads();

    int ty = tid >> 4, tx = tid & 15;
    float acc[4][4] = {};
#pragma unroll 8
    for (int d = 0; d < 64; d++) {
        int sw = d >> 2;
        float4 xv = *reinterpret_cast<float4*>(&Xt[d][(ty ^ sw) << 2]);
        float4 wv = *reinterpret_cast<float4*>(&Wt[d][(tx ^ sw) << 2]);
        float xa[4] = {xv.x, xv.y, xv.z, xv.w};
        float wa[4] = {wv.x, wv.y, wv.z, wv.w};
#pragma unroll
        for (int i = 0; i < 4; i++)
#pragma unroll
            for (int j = 0; j < 4; j++) acc[i][j] += xa[i] * wa[j];
    }

#pragma unroll
    for (int i = 0; i < 4; i++) {
        int r = r0 + ty * 4 + i;
        int b = r >> 15;
        int rem = r & 32767;
        int s = rem >> 4, h = rem & 15;
        float4 o;
        o.x = acc[i][0] + bs[tx*4+0];
        o.y = acc[i][1] + bs[tx*4+1];
        o.z = acc[i][2] + bs[tx*4+2];
        o.w = acc[i][3] + bs[tx*4+3];
        reinterpret_cast<float4*>(Y + ((size_t)(b*NH + h)*NS + s)*ND)[tx] = o;
    }
}

// ---------------------------------------------------------------------------
// Warp-MMA (m16n8k8 tf32) flash attention with FUSED threefry dropout.
// Block: 64 queries x head x batch, 128 threads = 4 warps (16 q-rows each).
// SMEM (uint32):
//   Kp [64 keys][72]: (d, d+4) pairs  -> one LDS.64 per QK B-frag
//   Vp [64 d   ][72]: (key, key+4) pairs -> one LDS.64 per PV B-frag
//   Ps [4 warps][16][68] (doubles as Q staging before the mainloop)
// ---------------------------------------------------------------------------
#define KP_OFF 0
#define VP_OFF 4608          /* 64*72 */
#define PS_OFF 9216          /* + 64*72 */
#define SMEM_WORDS 13568     /* + 4*16*68 */

__global__ __launch_bounds__(128, 3) void attn_mma_kernel(
        const float* __restrict__ mask, float* __restrict__ out) {
    extern __shared__ __align__(16) uint32_t sm[];
    uint32_t* Kp = sm + KP_OFF;
    uint32_t* Vp = sm + VP_OFF;
    uint32_t* Ps = sm + PS_OFF;

    int tid = threadIdx.x;
    int lane = tid & 31, w = tid >> 5;       // 4 warps
    int gi = lane >> 2, ci = lane & 3;
    int qt = blockIdx.x, h = blockIdx.y, b = blockIdx.z;
    int bh = b * NH + h;
    int q0 = qt * 64;

    int row = tid >> 1, hf = tid & 1;        // staging: 64 rows x 2 halves

    // ---- stage Q (scaled 1/8, tf32) into Ps region, then build A-fragments
    {
        const float4* Qg = reinterpret_cast<const float4*>(
            g_Q + ((size_t)bh * NS + q0 + row) * ND);
        uint32_t* dst = Ps + row * 68;
#pragma unroll
        for (int j = 0; j < 8; j++) {
            float4 v = Qg[hf * 8 + j];
            uint4 t;
            t.x = f2tf32(v.x * 0.125f); t.y = f2tf32(v.y * 0.125f);
            t.z = f2tf32(v.z * 0.125f); t.w = f2tf32(v.w * 0.125f);
            *reinterpret_cast<uint4*>(dst + (hf * 8 + j) * 4) = t;
        }
    }
    __syncthreads();
    uint32_t qf[8][4];
    {
        const uint32_t* Qs = Ps + (w * 16) * 68;
#pragma unroll
        for (int kc = 0; kc < 8; kc++) {
            qf[kc][0] = Qs[gi * 68 + kc * 8 + ci];
            qf[kc][1] = Qs[(gi + 8) * 68 + kc * 8 + ci];
            qf[kc][2] = Qs[gi * 68 + kc * 8 + ci + 4];
            qf[kc][3] = Qs[(gi + 8) * 68 + kc * 8 + ci + 4];
        }
    }

    float oacc[8][4] = {};
    float m_lo = -3.0e38f, m_hi = -3.0e38f, l_lo = 0.f, l_hi = 0.f;

    int rlo = q0 + w * 16 + gi, rhi = rlo + 8;
    const float* mask_lo = mask + ((size_t)b * NS + rlo) * NS;
    const float* mask_hi = mask + ((size_t)b * NS + rhi) * NS;
    // flat dropout-element base for this thread's two rows (fits in u32: <2^27)
    uint32_t ebl = (uint32_t)(bh * NS + rlo) * NS + 2 * ci;
    uint32_t ebh = (uint32_t)(bh * NS + rhi) * NS + 2 * ci;

    const float* Kbase = g_K + ((size_t)bh * NS + row) * ND;
    const float* Vbase = g_V + ((size_t)bh * NS + row) * ND;

    // V scatter destination for this thread (key = row):
    //  word offset within a d-row: kc*8 + ci*2 + half
    uint32_t v_woff = (uint32_t)((row >> 3) * 8 + (row & 3) * 2 + ((row >> 2) & 1));

    for (int kt = 0; kt < 32; kt++) {
        // ---- load K tile -> paired layout Kp[key][ (d,d+4) pairs ] ----
        {
            const float4* Kg = reinterpret_cast<const float4*>(
                Kbase + (size_t)kt * 64 * ND) + hf * 8;
            float4 t[8];
#pragma unroll
            for (int j = 0; j < 8; j++) t[j] = Kg[j];
#pragma unroll
            for (int kc = 0; kc < 4; kc++) {
                uint32_t* base = Kp + row * 72 + (4 * hf + kc) * 8;
                uint4 u0, u1;
                u0.x = f2tf32(t[2*kc].x); u0.y = f2tf32(t[2*kc+1].x);
                u0.z = f2tf32(t[2*kc].y); u0.w = f2tf32(t[2*kc+1].y);
                u1.x = f2tf32(t[2*kc].z); u1.y = f2tf32(t[2*kc+1].z);
                u1.z = f2tf32(t[2*kc].w); u1.w = f2tf32(t[2*kc+1].w);
                *reinterpret_cast<uint4*>(base) = u0;
                *reinterpret_cast<uint4*>(base + 4) = u1;
            }
            // ---- load V tile -> paired layout Vp[d][ (key,key+4) pairs ] ----
            const float4* Vg = reinterpret_cast<const float4*>(
                Vbase + (size_t)kt * 64 * ND) + hf * 8;
#pragma unroll
            for (int j = 0; j < 8; j++) t[j] = Vg[j];
#pragma unroll
            for (int j = 0; j < 8; j++) {
                int d0 = hf * 32 + j * 4;
                Vp[(d0+0) * 72 + v_woff] = f2tf32(t[j].x);
                Vp[(d0+1) * 72 + v_woff] = f2tf32(t[j].y);
                Vp[(d0+2) * 72 + v_woff] = f2tf32(t[j].z);
                Vp[(d0+3) * 72 + v_woff] = f2tf32(t[j].w);
            }
        }
        __syncthreads();

        // ---- S = Q @ K^T (B-frags: one LDS.64 each) ----
        float s[8][4] = {};
#pragma unroll
        for (int kc = 0; kc < 8; kc++) {
#pragma unroll
            for (int nt = 0; nt < 8; nt++) {
                uint2 bb = *reinterpret_cast<const uint2*>(
                    Kp + (nt * 8 + gi) * 72 + kc * 8 + ci * 2);
                mma8(s[nt], qf[kc], bb.x, bb.y);
            }
        }

        // ---- fused threefry dropout (fills tensor/LDS drain) ----
        uint32_t klo = 0u, khi = 0u;
        {
            uint32_t e0 = ebl + (uint32_t)kt * 64;
            uint32_t e1 = ebh + (uint32_t)kt * 64;
#pragma unroll 2
            for (int nt = 0; nt < 8; nt++) {
                klo |= keep2(e0 + nt * 8) << (2 * nt);
                khi |= keep2(e1 + nt * 8) << (2 * nt);
            }
        }

        // ---- mask + online softmax ----
        float mxl = -3.0e38f, mxh = -3.0e38f;
#pragma unroll
        for (int nt = 0; nt < 8; nt++) {
            float2 ml = *reinterpret_cast<const float2*>(
                mask_lo + kt * 64 + nt * 8 + 2 * ci);
            float2 mh = *reinterpret_cast<const float2*>(
                mask_hi + kt * 64 + nt * 8 + 2 * ci);
            s[nt][0] += ml.x; s[nt][1] += ml.y;
            s[nt][2] += mh.x; s[nt][3] += mh.y;
            mxl = fmaxf(mxl, fmaxf(s[nt][0], s[nt][1]));
            mxh = fmaxf(mxh, fmaxf(s[nt][2], s[nt][3]));
        }
        mxl = fmaxf(mxl, __shfl_xor_sync(0xffffffffu, mxl, 1));
        mxl = fmaxf(mxl, __shfl_xor_sync(0xffffffffu, mxl, 2));
        mxh = fmaxf(mxh, __shfl_xor_sync(0xffffffffu, mxh, 1));
        mxh = fmaxf(mxh, __shfl_xor_sync(0xffffffffu, mxh, 2));

        float nml = fmaxf(m_lo, mxl), nmh = fmaxf(m_hi, mxh);
        float scl = __expf(m_lo - nml), sch = __expf(m_hi - nmh);
        m_lo = nml; m_hi = nmh;

        float suml = 0.f, sumh = 0.f;
#pragma unroll
        for (int nt = 0; nt < 8; nt++) {
            s[nt][0] = __expf(s[nt][0] - nml);
            s[nt][1] = __expf(s[nt][1] - nml);
            s[nt][2] = __expf(s[nt][2] - nmh);
            s[nt][3] = __expf(s[nt][3] - nmh);
            suml += s[nt][0] + s[nt][1];
            sumh += s[nt][2] + s[nt][3];
        }
        suml += __shfl_xor_sync(0xffffffffu, suml, 1);
        suml += __shfl_xor_sync(0xffffffffu, suml, 2);
        sumh += __shfl_xor_sync(0xffffffffu, sumh, 1);
        sumh += __shfl_xor_sync(0xffffffffu, sumh, 2);
        l_lo = l_lo * scl + suml;
        l_hi = l_hi * sch + sumh;
#pragma unroll
        for (int nt = 0; nt < 8; nt++) {
            oacc[nt][0] *= scl; oacc[nt][1] *= scl;
            oacc[nt][2] *= sch; oacc[nt][3] *= sch;
        }

        // ---- dropout apply + P store (per-warp private region) ----
        uint32_t* Pw = Ps + w * 16 * 68;
#pragma unroll
        for (int nt = 0; nt < 8; nt++) {
            int c0 = nt * 8 + 2 * ci;
            uint2 plo, phi;
            plo.x = ((klo >> (2 * nt)) & 1u)     ? f2tf32(s[nt][0]) : 0u;
            plo.y = ((klo >> (2 * nt + 1)) & 1u) ? f2tf32(s[nt][1]) : 0u;
            phi.x = ((khi >> (2 * nt)) & 1u)     ? f2tf32(s[nt][2]) : 0u;
            phi.y = ((khi >> (2 * nt + 1)) & 1u) ? f2tf32(s[nt][3]) : 0u;
            *reinterpret_cast<uint2*>(Pw + gi * 68 + c0) = plo;
            *reinterpret_cast<uint2*>(Pw + (gi + 8) * 68 + c0) = phi;
        }
        __syncwarp();

        // ---- O += P @ V (B-frags: one LDS.64 each) ----
#pragma unroll
        for (int kc = 0; kc < 8; kc++) {
            uint32_t a[4];
            a[0] = Pw[gi * 68 + kc * 8 + ci];
            a[1] = Pw[(gi + 8) * 68 + kc * 8 + ci];
            a[2] = Pw[gi * 68 + kc * 8 + ci + 4];
            a[3] = Pw[(gi + 8) * 68 + kc * 8 + ci + 4];
#pragma unroll
            for (int nt = 0; nt < 8; nt++) {
                uint2 bb = *reinterpret_cast<const uint2*>(
                    Vp + (nt * 8 + gi) * 72 + kc * 8 + ci * 2);
                mma8(oacc[nt], a, bb.x, bb.y);
            }
        }
        __syncthreads();
    }

    // epilogue: out = oacc / (l * 0.9)
    float invl = 1.0f / (l_lo * 0.9f);
    float invh = 1.0f / (l_hi * 0.9f);
    float* out_lo = out + ((size_t)bh * NS + rlo) * ND;
    float* out_hi = out + ((size_t)bh * NS + rhi) * ND;
#pragma unroll
    for (int nt = 0; nt < 8; nt++) {
        float2 a, c;
        a.x = oacc[nt][0] * invl; a.y = oacc[nt][1] * invl;
        c.x = oacc[nt][2] * invh; c.y = oacc[nt][3] * invh;
        *reinterpret_cast<float2*>(out_lo + nt * 8 + 2 * ci) = a;
        *reinterpret_cast<float2*>(out_hi + nt * 8 + 2 * ci) = c;
    }
}

// ---------------------------------------------------------------------------
extern "C" void kernel_launch(void* const* d_in, const int* in_sizes, int n_in,
                              void* d_out, int out_size) {
    (void)in_sizes; (void)n_in; (void)out_size;
    const float* q   = (const float*)d_in[0];
    const float* k   = (const float*)d_in[1];
    const float* v   = (const float*)d_in[2];
    const float* msk = (const float*)d_in[3];
    const float* Wq  = (const float*)d_in[4];
    const float* bq  = (const float*)d_in[5];
    const float* Wk  = (const float*)d_in[6];
    const float* bk  = (const float*)d_in[7];
    const float* Wv  = (const float*)d_in[8];
    const float* bv  = (const float*)d_in[9];
    float* out = (float*)d_out;

    const int smem_bytes = SMEM_WORDS * 4;   // 54272 B
    cudaFuncSetAttribute(attn_mma_kernel,
                         cudaFuncAttributeMaxDynamicSharedMemorySize, smem_bytes);

    proj_kernel<<<1024, 256>>>(q, Wq, bq, 0);
    proj_kernel<<<1024, 256>>>(k, Wk, bk, 1);
    proj_kernel<<<1024, 256>>>(v, Wv, bv, 2);

    dim3 grid(NS / 64, NH, NB);
    attn_mma_kernel<<<grid, 128, smem_bytes>>>(msk, out);
}